// round 6
// baseline (speedup 1.0000x reference)
#include <cuda_runtime.h>
#include <cuda_bf16.h>
#include <cstdint>

// BaseVectorQuantizer: bf16 mma.sync (legacy HMMA, baseline PTX) screening
// + exact fp32 re-check.  dist_k = fp32( fp32(||x||^2+||e_k||^2) - 2*dot ).

#define NUM_K 1024
#define DIM   64
#define HW    4096
#define NVEC  131072
#define TPB   128
#define CK    128          // codes per chunk
#define NCHUNK 8
#define ROWB  144          // padded smem row stride (bytes) for 64 bf16 dims
#define NSLOT 6

// dynamic smem layout
#define S_A   0            // x bf16 padded rows           18432
#define S_B0  18432        // codebook chunk buf0          18432
#define S_B1  36864        // codebook chunk buf1          18432
#define S_X   55296        // x fp32 [dim][vec]            32768
#define S_SE  88064        // esq[1024]                     4096
#define S_XQ  92160        // xsq[128]                       512
#define S_SB  92672        // sabs[128]                      512
#define S_SK  93184        // chosen k[128]                  512
#define S_TOTAL 93696

__device__ float        g_esq[NUM_K];
__device__ unsigned int g_cbb[NUM_K * DIM / 2];   // bf16x2-packed codebook rows
__device__ int          g_maxe_i = 0;

__device__ __forceinline__ uint32_t smem_u32(const void* p) {
    uint32_t a;
    asm("{ .reg .u64 t; cvta.to.shared.u64 t, %1; cvt.u32.u64 %0, t; }" : "=r"(a) : "l"(p));
    return a;
}
__device__ __forceinline__ void ldsm_x4(uint32_t* r, uint32_t addr) {
    asm volatile("ldmatrix.sync.aligned.m8n8.x4.shared.b16 {%0,%1,%2,%3}, [%4];"
                 : "=r"(r[0]), "=r"(r[1]), "=r"(r[2]), "=r"(r[3]) : "r"(addr));
}
__device__ __forceinline__ void mma16816(float* d, const uint32_t* a, const uint32_t* b) {
    asm volatile("mma.sync.aligned.m16n8k16.row.col.f32.bf16.bf16.f32 "
                 "{%0,%1,%2,%3}, {%4,%5,%6,%7}, {%8,%9}, {%0,%1,%2,%3};"
                 : "+f"(d[0]), "+f"(d[1]), "+f"(d[2]), "+f"(d[3])
                 : "r"(a[0]), "r"(a[1]), "r"(a[2]), "r"(a[3]), "r"(b[0]), "r"(b[1]));
}

// ---------------- prep: exact esq, bf16 codebook, max|e| ----------------
__global__ void prep_kernel(const float* __restrict__ cb) {
    int k = blockIdx.x * blockDim.x + threadIdx.x;
    if (k >= NUM_K) return;
    const float* r = cb + k * DIM;
    float s = 0.f, mx = 0.f;
    #pragma unroll
    for (int p = 0; p < DIM / 2; p++) {
        float v0 = r[2 * p], v1 = r[2 * p + 1];
        s = __fadd_rn(s, __fmul_rn(v0, v0));
        s = __fadd_rn(s, __fmul_rn(v1, v1));
        mx = fmaxf(mx, fmaxf(fabsf(v0), fabsf(v1)));
        __nv_bfloat162 h2 = __floats2bfloat162_rn(v0, v1);   // v0 low, v1 high
        g_cbb[k * (DIM / 2) + p] = *reinterpret_cast<unsigned int*>(&h2);
    }
    g_esq[k] = s;
    atomicMax(&g_maxe_i, __float_as_int(mx));
}

// exact reference-rounded distance (identical chain to the verified R3 kernel)
__device__ __forceinline__ float exact_dist(const float* __restrict__ cb,
                                            const float* __restrict__ sx,
                                            int v, float xsq, int k) {
    const float4* er = reinterpret_cast<const float4*>(cb + (size_t)k * DIM);
    float dot = 0.f;
    #pragma unroll
    for (int j = 0; j < 16; j++) {
        float4 e = __ldg(er + j);
        dot = fmaf(sx[(4 * j + 0) * TPB + v], e.x, dot);
        dot = fmaf(sx[(4 * j + 1) * TPB + v], e.y, dot);
        dot = fmaf(sx[(4 * j + 2) * TPB + v], e.z, dot);
        dot = fmaf(sx[(4 * j + 3) * TPB + v], e.w, dot);
    }
    float tt = __fadd_rn(xsq, __ldg(&g_esq[k]));
    return __fsub_rn(tt, __fadd_rn(dot, dot));
}

__global__ __launch_bounds__(TPB) void vq_kernel(const float* __restrict__ x_in,
                                                 const float* __restrict__ cb,
                                                 float* __restrict__ out) {
    extern __shared__ char smem[];
    const uint32_t sb = smem_u32(smem);
    float* sx  = reinterpret_cast<float*>(smem + S_X);
    float* se  = reinterpret_cast<float*>(smem + S_SE);
    float* sxq = reinterpret_cast<float*>(smem + S_XQ);
    float* ssb = reinterpret_cast<float*>(smem + S_SB);
    int*   sk  = reinterpret_cast<int*>(smem + S_SK);

    const int t    = threadIdx.x;
    const int lane = t & 31;
    const int w    = t >> 5;
    const int r    = lane >> 2;     // D-fragment row group
    const int cq   = lane & 3;      // D-fragment col group
    const int base = blockIdx.x * TPB;
    const int b    = base >> 12;
    const int s    = (base & (HW - 1)) + t;

    // ---- stage x: bf16 padded rows (for ldmatrix A) + fp32 transposed + xsq/sabs ----
    {
        const float* xp = x_in + (size_t)b * (DIM * HW) + s;
        float xsq = 0.f, sabs = 0.f;
        char* arow = smem + S_A + t * ROWB;
        #pragma unroll
        for (int p = 0; p < DIM / 2; p++) {
            float v0 = xp[(2 * p) * HW], v1 = xp[(2 * p + 1) * HW];
            xsq = __fadd_rn(xsq, __fmul_rn(v0, v0));
            xsq = __fadd_rn(xsq, __fmul_rn(v1, v1));
            sabs += fabsf(v0) + fabsf(v1);
            sx[(2 * p) * TPB + t] = v0;
            sx[(2 * p + 1) * TPB + t] = v1;
            __nv_bfloat162 h2 = __floats2bfloat162_rn(v0, v1);
            *reinterpret_cast<unsigned int*>(arow + p * 4) =
                *reinterpret_cast<unsigned int*>(&h2);
        }
        sxq[t] = xsq;
        ssb[t] = sabs;
        // esq table
        #pragma unroll
        for (int i = 0; i < NUM_K / TPB; i++) se[i * TPB + t] = g_esq[i * TPB + t];
        // codebook chunk 0 (straight copy — R5 had a corrupting stray store here)
        const uint4* src = reinterpret_cast<const uint4*>(&g_cbb[(size_t)t * (DIM / 2)]);
        char* brow = smem + S_B0 + t * ROWB;
        #pragma unroll
        for (int q = 0; q < 8; q++)
            *reinterpret_cast<uint4*>(brow + q * 16) = __ldg(src + q);
    }
    __syncthreads();

    // ---- load A fragments once: a[mt][kt][4] ----
    uint32_t afr[2][4][4];
    #pragma unroll
    for (int mt = 0; mt < 2; mt++)
        #pragma unroll
        for (int kt = 0; kt < 4; kt++) {
            uint32_t addr = sb + S_A + (32 * w + 16 * mt + (lane & 15)) * ROWB
                          + kt * 32 + (lane >> 4) * 16;
            ldsm_x4(afr[mt][kt], addr);
        }

    const float maxe = __int_as_float(g_maxe_i);
    float xsqs[4], margs[4], bests[4];
    int   ncs[4];
    int   cand[4][NSLOT];
    #pragma unroll
    for (int sv = 0; sv < 4; sv++) {
        int v = 32 * w + 16 * (sv >> 1) + 8 * (sv & 1) + r;
        xsqs[sv]  = sxq[v];
        // sound band: 2*eps = 2^-5 * sum|x| * max|e|; 0.04 gives >=1.28x safety; +slop
        margs[sv] = ssb[v] * maxe * 0.04f + 2e-4f;
        bests[sv] = 3.4e38f;
        ncs[sv]   = 0;
    }

    // ---- main loop: 8 chunks x 16 n8-tiles ----
    for (int c = 0; c < NCHUNK; c++) {
        // prefetch next chunk into other buffer
        if (c + 1 < NCHUNK) {
            const uint4* src = reinterpret_cast<const uint4*>(
                &g_cbb[(size_t)((c + 1) * CK + t) * (DIM / 2)]);
            char* brow = smem + (((c + 1) & 1) ? S_B1 : S_B0) + t * ROWB;
            #pragma unroll
            for (int q = 0; q < 8; q++)
                *reinterpret_cast<uint4*>(brow + q * 16) = __ldg(src + q);
        }
        const uint32_t sbB = sb + ((c & 1) ? S_B1 : S_B0);
        const int nto  = (lane >> 4) & 1;          // ldmatrix.x4: which nt of the pair
        const int kh   = (lane >> 3) & 1;          // which k-half

        #pragma unroll 1
        for (int ntp = 0; ntp < 8; ntp++) {
            uint32_t bfr[4][4];
            #pragma unroll
            for (int kt = 0; kt < 4; kt++) {
                uint32_t addr = sbB + (8 * (2 * ntp + nto) + (lane & 7)) * ROWB
                              + kt * 32 + kh * 16;
                ldsm_x4(bfr[kt], addr);
            }
            #pragma unroll
            for (int h = 0; h < 2; h++) {
                const int nt = 2 * ntp + h;
                const float2 eq = *reinterpret_cast<const float2*>(
                    &se[c * CK + nt * 8 + 2 * cq]);
                const int k0 = c * CK + nt * 8 + 2 * cq;
                #pragma unroll
                for (int mt = 0; mt < 2; mt++) {
                    float d[4] = {0.f, 0.f, 0.f, 0.f};
                    #pragma unroll
                    for (int kt = 0; kt < 4; kt++) {
                        uint32_t bb[2] = {bfr[kt][2 * h], bfr[kt][2 * h + 1]};
                        mma16816(d, afr[mt][kt], bb);
                    }
                    #pragma unroll
                    for (int hh = 0; hh < 2; hh++) {       // row r (hh=0) / r+8 (hh=1)
                        const int sv = mt * 2 + hh;
                        float di0 = fmaf(-2.f, d[2 * hh + 0], xsqs[sv] + eq.x);
                        float di1 = fmaf(-2.f, d[2 * hh + 1], xsqs[sv] + eq.y);
                        float thr = bests[sv] + margs[sv];
                        if (di0 < thr) { if (ncs[sv] < NSLOT) cand[sv][ncs[sv]] = k0;     ncs[sv]++; }
                        if (di1 < thr) { if (ncs[sv] < NSLOT) cand[sv][ncs[sv]] = k0 + 1; ncs[sv]++; }
                        bests[sv] = fminf(bests[sv], fminf(di0, di1));
                    }
                }
            }
        }
        __syncthreads();
    }

    // ---- exact re-check + quad reduction ----
    #pragma unroll
    for (int sv = 0; sv < 4; sv++) {
        const int v = 32 * w + 16 * (sv >> 1) + 8 * (sv & 1) + r;
        float dE = 3.4e38f;
        int   bk = NUM_K;
        if (ncs[sv] <= NSLOT) {
            #pragma unroll
            for (int i = 0; i < NSLOT; i++)
                if (i < ncs[sv]) {
                    int k = cand[sv][i];
                    float d = exact_dist(cb, sx, v, xsqs[sv], k);
                    if (d < dE || (d == dE && k < bk)) { dE = d; bk = k; }
                }
        } else {                                   // sound fallback (rare)
            for (int k = 0; k < NUM_K; k++) {
                float d = exact_dist(cb, sx, v, xsqs[sv], k);
                if (d < dE) { dE = d; bk = k; }
            }
        }
        #pragma unroll
        for (int off = 1; off <= 2; off <<= 1) {
            float od = __shfl_xor_sync(0xffffffff, dE, off);
            int   ok = __shfl_xor_sync(0xffffffff, bk, off);
            if (od < dE || (od == dE && ok < bk)) { dE = od; bk = ok; }
        }
        if (cq == 0) sk[v] = bk;
    }
    __syncthreads();

    // ---- STE epilogue: thread t owns vector t (coalesced BCHW scatter) ----
    const int bk = sk[t];
    const float4* row = reinterpret_cast<const float4*>(cb + (size_t)bk * DIM);
    float* op = out + (size_t)b * (DIM * HW) + s;
    #pragma unroll
    for (int j = 0; j < DIM / 4; j++) {
        float4 qv = __ldg(row + j);
        float x0 = sx[(4 * j + 0) * TPB + t];
        float x1 = sx[(4 * j + 1) * TPB + t];
        float x2 = sx[(4 * j + 2) * TPB + t];
        float x3 = sx[(4 * j + 3) * TPB + t];
        op[(4 * j + 0) * HW] = __fadd_rn(x0, __fsub_rn(qv.x, x0));
        op[(4 * j + 1) * HW] = __fadd_rn(x1, __fsub_rn(qv.y, x1));
        op[(4 * j + 2) * HW] = __fadd_rn(x2, __fsub_rn(qv.z, x2));
        op[(4 * j + 3) * HW] = __fadd_rn(x3, __fsub_rn(qv.w, x3));
    }
}

extern "C" void kernel_launch(void* const* d_in, const int* in_sizes, int n_in,
                              void* d_out, int out_size) {
    const float* x  = (const float*)d_in[0];
    const float* cb = (const float*)d_in[1];
    if (n_in >= 2 && in_sizes[0] == NUM_K * DIM && in_sizes[1] == NVEC * DIM) {
        const float* t = x; x = cb; cb = t;
    }
    float* out = (float*)d_out;

    cudaFuncSetAttribute(vq_kernel, cudaFuncAttributeMaxDynamicSharedMemorySize, S_TOTAL);
    prep_kernel<<<NUM_K / 128, 128>>>(cb);
    vq_kernel<<<NVEC / TPB, TPB, S_TOTAL>>>(x, cb, out);
}

// round 7
// speedup vs baseline: 2.5213x; 2.5213x over previous
#include <cuda_runtime.h>
#include <cuda_bf16.h>
#include <cstdint>

// BaseVectorQuantizer: bf16 mma.sync (legacy HMMA, baseline PTX) screening
// + exact fp32 re-check.  dist_k = fp32( fp32(||x||^2+||e_k||^2) - 2*dot ).
// Two-pass screen: pass A finds min(approx), pass B collects candidates
// within a fixed sound band (avoids running-minima candidate pollution).

#define NUM_K 1024
#define DIM   64
#define HW    4096
#define NVEC  131072
#define TPB   128
#define CK    128          // codes per chunk
#define NCHUNK 8
#define ROWB  144          // padded smem row stride (bytes) for 64 bf16 dims
#define NSLOT 6

// dynamic smem layout
#define S_A   0            // x bf16 padded rows           18432
#define S_B0  18432        // codebook chunk buf0          18432
#define S_B1  36864        // codebook chunk buf1          18432
#define S_X   55296        // x fp32 [dim][vec]            32768
#define S_SE  88064        // esq[1024]                     4096
#define S_XQ  92160        // xsq[128]                       512
#define S_SB  92672        // sabs[128]                      512
#define S_SK  93184        // chosen k[128]                  512
#define S_TOTAL 93696

__device__ float        g_esq[NUM_K];
__device__ unsigned int g_cbb[NUM_K * DIM / 2];   // bf16x2-packed codebook rows
__device__ int          g_maxe_i = 0;

__device__ __forceinline__ uint32_t smem_u32(const void* p) {
    uint32_t a;
    asm("{ .reg .u64 t; cvta.to.shared.u64 t, %1; cvt.u32.u64 %0, t; }" : "=r"(a) : "l"(p));
    return a;
}
__device__ __forceinline__ void ldsm_x4(uint32_t* r, uint32_t addr) {
    asm volatile("ldmatrix.sync.aligned.m8n8.x4.shared.b16 {%0,%1,%2,%3}, [%4];"
                 : "=r"(r[0]), "=r"(r[1]), "=r"(r[2]), "=r"(r[3]) : "r"(addr));
}
__device__ __forceinline__ void mma16816(float* d, const uint32_t* a, const uint32_t* b) {
    asm volatile("mma.sync.aligned.m16n8k16.row.col.f32.bf16.bf16.f32 "
                 "{%0,%1,%2,%3}, {%4,%5,%6,%7}, {%8,%9}, {%0,%1,%2,%3};"
                 : "+f"(d[0]), "+f"(d[1]), "+f"(d[2]), "+f"(d[3])
                 : "r"(a[0]), "r"(a[1]), "r"(a[2]), "r"(a[3]), "r"(b[0]), "r"(b[1]));
}

// ---------------- prep: exact esq, bf16 codebook, max|e| ----------------
__global__ void prep_kernel(const float* __restrict__ cb) {
    int k = blockIdx.x * blockDim.x + threadIdx.x;
    if (k >= NUM_K) return;
    const float* r = cb + k * DIM;
    float s = 0.f, mx = 0.f;
    #pragma unroll
    for (int p = 0; p < DIM / 2; p++) {
        float v0 = r[2 * p], v1 = r[2 * p + 1];
        s = __fadd_rn(s, __fmul_rn(v0, v0));
        s = __fadd_rn(s, __fmul_rn(v1, v1));
        mx = fmaxf(mx, fmaxf(fabsf(v0), fabsf(v1)));
        __nv_bfloat162 h2 = __floats2bfloat162_rn(v0, v1);   // v0 low, v1 high
        g_cbb[k * (DIM / 2) + p] = *reinterpret_cast<unsigned int*>(&h2);
    }
    g_esq[k] = s;
    atomicMax(&g_maxe_i, __float_as_int(mx));
}

// exact reference-rounded distance (identical chain to the verified R2/R3 kernels)
__device__ __forceinline__ float exact_dist(const float* __restrict__ cb,
                                            const float* __restrict__ sx,
                                            int v, float xsq, int k) {
    const float4* er = reinterpret_cast<const float4*>(cb + (size_t)k * DIM);
    float dot = 0.f;
    #pragma unroll
    for (int j = 0; j < 16; j++) {
        float4 e = __ldg(er + j);
        dot = fmaf(sx[(4 * j + 0) * TPB + v], e.x, dot);
        dot = fmaf(sx[(4 * j + 1) * TPB + v], e.y, dot);
        dot = fmaf(sx[(4 * j + 2) * TPB + v], e.z, dot);
        dot = fmaf(sx[(4 * j + 3) * TPB + v], e.w, dot);
    }
    float tt = __fadd_rn(xsq, __ldg(&g_esq[k]));
    return __fsub_rn(tt, __fadd_rn(dot, dot));
}

__global__ __launch_bounds__(TPB) void vq_kernel(const float* __restrict__ x_in,
                                                 const float* __restrict__ cb,
                                                 float* __restrict__ out) {
    extern __shared__ char smem[];
    const uint32_t sb = smem_u32(smem);
    float* sx  = reinterpret_cast<float*>(smem + S_X);
    float* se  = reinterpret_cast<float*>(smem + S_SE);
    float* sxq = reinterpret_cast<float*>(smem + S_XQ);
    float* ssb = reinterpret_cast<float*>(smem + S_SB);
    int*   sk  = reinterpret_cast<int*>(smem + S_SK);

    const int t    = threadIdx.x;
    const int lane = t & 31;
    const int w    = t >> 5;
    const int r    = lane >> 2;     // D-fragment row group
    const int cq   = lane & 3;      // D-fragment col group
    const int base = blockIdx.x * TPB;
    const int b    = base >> 12;
    const int s    = (base & (HW - 1)) + t;

    // ---- stage x: bf16 padded rows (ldmatrix A) + fp32 transposed + xsq/sabs ----
    {
        const float* xp = x_in + (size_t)b * (DIM * HW) + s;
        float xsq = 0.f, sabs = 0.f;
        char* arow = smem + S_A + t * ROWB;
        #pragma unroll
        for (int p = 0; p < DIM / 2; p++) {
            float v0 = xp[(2 * p) * HW], v1 = xp[(2 * p + 1) * HW];
            xsq = __fadd_rn(xsq, __fmul_rn(v0, v0));
            xsq = __fadd_rn(xsq, __fmul_rn(v1, v1));
            sabs += fabsf(v0) + fabsf(v1);
            sx[(2 * p) * TPB + t] = v0;
            sx[(2 * p + 1) * TPB + t] = v1;
            __nv_bfloat162 h2 = __floats2bfloat162_rn(v0, v1);
            *reinterpret_cast<unsigned int*>(arow + p * 4) =
                *reinterpret_cast<unsigned int*>(&h2);
        }
        sxq[t] = xsq;
        ssb[t] = sabs;
        #pragma unroll
        for (int i = 0; i < NUM_K / TPB; i++) se[i * TPB + t] = g_esq[i * TPB + t];
        // codebook chunk 0
        const uint4* src = reinterpret_cast<const uint4*>(&g_cbb[(size_t)t * (DIM / 2)]);
        char* brow = smem + S_B0 + t * ROWB;
        #pragma unroll
        for (int q = 0; q < 8; q++)
            *reinterpret_cast<uint4*>(brow + q * 16) = __ldg(src + q);
    }
    __syncthreads();

    // ---- load A fragments once: a[mt][kt][4] ----
    uint32_t afr[2][4][4];
    #pragma unroll
    for (int mt = 0; mt < 2; mt++)
        #pragma unroll
        for (int kt = 0; kt < 4; kt++) {
            uint32_t addr = sb + S_A + (32 * w + 16 * mt + (lane & 15)) * ROWB
                          + kt * 32 + (lane >> 4) * 16;
            ldsm_x4(afr[mt][kt], addr);
        }

    const float maxe = __int_as_float(g_maxe_i);
    float xsqs[4], margs[4], bests[4], thrB[4];
    int   ncs[4];
    int   cand[4][NSLOT];
    #pragma unroll
    for (int sv = 0; sv < 4; sv++) {
        int v = 32 * w + 16 * (sv >> 1) + 8 * (sv & 1) + r;
        xsqs[sv]  = sxq[v];
        // sound band: 2*eps = 2^-5 * sum|x| * max|e|; 0.04 -> >=1.28x safety; + slop
        margs[sv] = ssb[v] * maxe * 0.04f + 2e-4f;
        bests[sv] = 3.4e38f;
        thrB[sv]  = 3.4e38f;
        ncs[sv]   = 0;
    }

    const int nto = (lane >> 4) & 1;
    const int kh  = (lane >> 3) & 1;

    // ---- two passes: pass 0 = min only; pass 1 = collect vs fixed band ----
    #pragma unroll 1
    for (int pass = 0; pass < 2; pass++) {
        const bool collect = (pass == 1);
        #pragma unroll 1
        for (int c = 0; c < NCHUNK; c++) {
            // cyclic prefetch: during (pass0, c=7) this stages chunk 0 for pass 1
            if (!(pass == 1 && c == NCHUNK - 1)) {
                const int nc1 = (c + 1) & (NCHUNK - 1);
                const uint4* src = reinterpret_cast<const uint4*>(
                    &g_cbb[(size_t)(nc1 * CK + t) * (DIM / 2)]);
                char* brow = smem + ((nc1 & 1) ? S_B1 : S_B0) + t * ROWB;
                #pragma unroll
                for (int q = 0; q < 8; q++)
                    *reinterpret_cast<uint4*>(brow + q * 16) = __ldg(src + q);
            }
            const uint32_t sbB = sb + ((c & 1) ? S_B1 : S_B0);

            #pragma unroll 1
            for (int ntp = 0; ntp < 8; ntp++) {
                uint32_t bfr[4][4];
                #pragma unroll
                for (int kt = 0; kt < 4; kt++) {
                    uint32_t addr = sbB + (8 * (2 * ntp + nto) + (lane & 7)) * ROWB
                                  + kt * 32 + kh * 16;
                    ldsm_x4(bfr[kt], addr);
                }
                #pragma unroll
                for (int h = 0; h < 2; h++) {
                    const int nt = 2 * ntp + h;
                    const float2 eq = *reinterpret_cast<const float2*>(
                        &se[c * CK + nt * 8 + 2 * cq]);
                    const int k0 = c * CK + nt * 8 + 2 * cq;
                    #pragma unroll
                    for (int mt = 0; mt < 2; mt++) {
                        float d[4] = {0.f, 0.f, 0.f, 0.f};
                        #pragma unroll
                        for (int kt = 0; kt < 4; kt++) {
                            uint32_t bb[2] = {bfr[kt][2 * h], bfr[kt][2 * h + 1]};
                            mma16816(d, afr[mt][kt], bb);
                        }
                        #pragma unroll
                        for (int hh = 0; hh < 2; hh++) {   // row r / r+8
                            const int sv = mt * 2 + hh;
                            float di0 = fmaf(-2.f, d[2 * hh + 0], xsqs[sv] + eq.x);
                            float di1 = fmaf(-2.f, d[2 * hh + 1], xsqs[sv] + eq.y);
                            if (collect) {
                                if (di0 < thrB[sv]) {
                                    if (ncs[sv] < NSLOT) cand[sv][ncs[sv]] = k0;
                                    ncs[sv]++;
                                }
                                if (di1 < thrB[sv]) {
                                    if (ncs[sv] < NSLOT) cand[sv][ncs[sv]] = k0 + 1;
                                    ncs[sv]++;
                                }
                            } else {
                                bests[sv] = fminf(bests[sv], fminf(di0, di1));
                            }
                        }
                    }
                }
            }
            __syncthreads();
        }
        if (pass == 0) {
            #pragma unroll
            for (int sv = 0; sv < 4; sv++) thrB[sv] = bests[sv] + margs[sv];
        }
    }

    // ---- exact re-check + quad reduction ----
    #pragma unroll
    for (int sv = 0; sv < 4; sv++) {
        const int v = 32 * w + 16 * (sv >> 1) + 8 * (sv & 1) + r;
        float dE = 3.4e38f;
        int   bk = NUM_K;
        if (ncs[sv] <= NSLOT) {
            #pragma unroll
            for (int i = 0; i < NSLOT; i++)
                if (i < ncs[sv]) {
                    int k = cand[sv][i];
                    float d = exact_dist(cb, sx, v, xsqs[sv], k);
                    if (d < dE || (d == dE && k < bk)) { dE = d; bk = k; }
                }
        } else {                                   // sound fallback (now rare)
            for (int k = 0; k < NUM_K; k++) {
                float d = exact_dist(cb, sx, v, xsqs[sv], k);
                if (d < dE) { dE = d; bk = k; }
            }
        }
        #pragma unroll
        for (int off = 1; off <= 2; off <<= 1) {
            float od = __shfl_xor_sync(0xffffffff, dE, off);
            int   ok = __shfl_xor_sync(0xffffffff, bk, off);
            if (od < dE || (od == dE && ok < bk)) { dE = od; bk = ok; }
        }
        if (cq == 0) sk[v] = bk;
    }
    __syncthreads();

    // ---- STE epilogue: thread t owns vector t (coalesced BCHW scatter) ----
    const int bk = sk[t];
    const float4* row = reinterpret_cast<const float4*>(cb + (size_t)bk * DIM);
    float* op = out + (size_t)b * (DIM * HW) + s;
    #pragma unroll
    for (int j = 0; j < DIM / 4; j++) {
        float4 qv = __ldg(row + j);
        float x0 = sx[(4 * j + 0) * TPB + t];
        float x1 = sx[(4 * j + 1) * TPB + t];
        float x2 = sx[(4 * j + 2) * TPB + t];
        float x3 = sx[(4 * j + 3) * TPB + t];
        op[(4 * j + 0) * HW] = __fadd_rn(x0, __fsub_rn(qv.x, x0));
        op[(4 * j + 1) * HW] = __fadd_rn(x1, __fsub_rn(qv.y, x1));
        op[(4 * j + 2) * HW] = __fadd_rn(x2, __fsub_rn(qv.z, x2));
        op[(4 * j + 3) * HW] = __fadd_rn(x3, __fsub_rn(qv.w, x3));
    }
}

extern "C" void kernel_launch(void* const* d_in, const int* in_sizes, int n_in,
                              void* d_out, int out_size) {
    const float* x  = (const float*)d_in[0];
    const float* cb = (const float*)d_in[1];
    if (n_in >= 2 && in_sizes[0] == NUM_K * DIM && in_sizes[1] == NVEC * DIM) {
        const float* t = x; x = cb; cb = t;
    }
    float* out = (float*)d_out;

    cudaFuncSetAttribute(vq_kernel, cudaFuncAttributeMaxDynamicSharedMemorySize, S_TOTAL);
    prep_kernel<<<NUM_K / 128, 128>>>(cb);
    vq_kernel<<<NVEC / TPB, TPB, S_TOTAL>>>(x, cb, out);
}

// round 8
// speedup vs baseline: 9.2566x; 3.6714x over previous
#include <cuda_runtime.h>
#include <cstdint>

// BaseVectorQuantizer, exact: dist_k = fp32( fp32(||x||^2+||e_k||^2) - 2*dot ).
// FFMA2 main loop computes cheap screen s_k = fma(-2,dot,esq) (xsq-free),
// tracks top-3; sound band test resolves winner, rare exact recheck/full scan.

#define NUM_K 1024
#define DIM   64
#define CHUNK 128
#define TPB   128
#define HW    4096
#define NVEC  131072
#define VPB   256
#define BAND  2.5e-5f

typedef unsigned long long ull_t;

__device__ float g_esq[NUM_K];

__global__ void esq_kernel(const float* __restrict__ cb) {
    int k = blockIdx.x * blockDim.x + threadIdx.x;
    if (k < NUM_K) {
        float s = 0.f;
        #pragma unroll
        for (int i = 0; i < DIM; i++) {
            float v = cb[k * DIM + i];
            s = __fadd_rn(s, __fmul_rn(v, v));
        }
        g_esq[k] = s;
    }
}

// exact reference-rounded distance; x held as packed f32x2 dim-pairs in regs
__device__ __forceinline__ float exact_k(const float* __restrict__ cb,
                                         const ull_t* __restrict__ x2,
                                         float xsq, int k) {
    const float4* er = reinterpret_cast<const float4*>(cb + (size_t)k * DIM);
    float d0 = 0.f, d1 = 0.f, d2 = 0.f, d3 = 0.f;
    #pragma unroll
    for (int j = 0; j < 16; j++) {
        float4 e = __ldg(er + j);
        float x0, x1, x2v, x3;
        asm("mov.b64 {%0, %1}, %2;" : "=f"(x0), "=f"(x1) : "l"(x2[2 * j]));
        asm("mov.b64 {%0, %1}, %2;" : "=f"(x2v), "=f"(x3) : "l"(x2[2 * j + 1]));
        d0 = fmaf(x0, e.x, d0);
        d1 = fmaf(x1, e.y, d1);
        d2 = fmaf(x2v, e.z, d2);
        d3 = fmaf(x3, e.w, d3);
    }
    float dot = __fadd_rn(__fadd_rn(d0, d1), __fadd_rn(d2, d3));
    float tt  = __fadd_rn(xsq, __ldg(&g_esq[k]));
    return __fsub_rn(tt, __fadd_rn(dot, dot));
}

__device__ __forceinline__ int resolve(const float* __restrict__ cb,
                                       const ull_t* __restrict__ x2, float xsq,
                                       float s1, float s2, float s3,
                                       int k1, int k2, int k3) {
    (void)k3;
    if (s2 > s1 + BAND) return k1;                 // provably unique winner
    if (s3 > s1 + BAND) {                          // two candidates, exact duel
        float e1 = exact_k(cb, x2, xsq, k1);
        float e2 = exact_k(cb, x2, xsq, k2);
        return (e2 < e1 || (e2 == e1 && k2 < k1)) ? k2 : k1;
    }
    float dE = 3.4e38f;                            // rare sound fallback
    int   bk = 0;
    for (int k = 0; k < NUM_K; k++) {
        float d = exact_k(cb, x2, xsq, k);
        if (d < dE) { dE = d; bk = k; }
    }
    return bk;
}

__global__ __launch_bounds__(TPB, 3) void vq_kernel(const float* __restrict__ x_in,
                                                    const float* __restrict__ cb,
                                                    float* __restrict__ out) {
    __shared__ __align__(16) float se[CHUNK * DIM];   // 32 KB, row-major
    __shared__ float sesq[CHUNK];

    const int t    = threadIdx.x;
    const int base = blockIdx.x * VPB;
    const int b    = base >> 12;
    const int sA   = (base & (HW - 1)) + t;
    const float* xpA = x_in + (size_t)b * (DIM * HW) + sA;
    const float* xpB = xpA + TPB;

    ull_t xA2[DIM / 2], xB2[DIM / 2];
    float xsqA = 0.f, xsqB = 0.f;
    #pragma unroll
    for (int p = 0; p < DIM / 2; p++) {
        float a0 = xpA[(2 * p) * HW], a1 = xpA[(2 * p + 1) * HW];
        float c0 = xpB[(2 * p) * HW], c1 = xpB[(2 * p + 1) * HW];
        xsqA = __fadd_rn(xsqA, __fmul_rn(a0, a0));
        xsqA = __fadd_rn(xsqA, __fmul_rn(a1, a1));
        xsqB = __fadd_rn(xsqB, __fmul_rn(c0, c0));
        xsqB = __fadd_rn(xsqB, __fmul_rn(c1, c1));
        asm("mov.b64 %0, {%1, %2};" : "=l"(xA2[p]) : "f"(a0), "f"(a1));
        asm("mov.b64 %0, {%1, %2};" : "=l"(xB2[p]) : "f"(c0), "f"(c1));
    }

    uint32_t se_base;
    asm("{ .reg .u64 t; cvta.to.shared.u64 t, %1; cvt.u32.u64 %0, t; }"
        : "=r"(se_base) : "l"(se));

    // top-3 screen state per vector
    float s1A = 3.4e38f, s2A = 3.4e38f, s3A = 3.4e38f;
    float s1B = 3.4e38f, s2B = 3.4e38f, s3B = 3.4e38f;
    int   k1A = 0, k2A = 0, k3A = 0, k1B = 0, k2B = 0, k3B = 0;

    #define INS(s, kk, s1, s2, s3, k1, k2, k3)                         \
        if ((s) < (s3)) {                                              \
            if ((s) < (s2)) {                                          \
                s3 = s2; k3 = k2;                                      \
                if ((s) < (s1)) { s2 = s1; k2 = k1; s1 = (s); k1 = (kk); } \
                else            { s2 = (s); k2 = (kk); }               \
            } else { s3 = (s); k3 = (kk); }                            \
        }

    for (int c = 0; c < NUM_K / CHUNK; c++) {
        __syncthreads();
        const float4* src = reinterpret_cast<const float4*>(cb + c * CHUNK * DIM);
        float4* dst = reinterpret_cast<float4*>(se);
        #pragma unroll
        for (int j = 0; j < (CHUNK * DIM / 4) / TPB; j++)
            dst[j * TPB + t] = src[j * TPB + t];
        sesq[t] = g_esq[c * CHUNK + t];
        __syncthreads();

        #pragma unroll 2
        for (int k = 0; k < CHUNK; k++) {
            ull_t a0 = 0ull, a1 = 0ull, b0 = 0ull, b1 = 0ull;
            const uint32_t addr = se_base + k * (DIM * 4);
            #pragma unroll
            for (int d4 = 0; d4 < DIM / 4; d4++) {
                ull_t e0, e1;
                asm("ld.shared.v2.u64 {%0, %1}, [%2];"
                    : "=l"(e0), "=l"(e1) : "r"(addr + d4 * 16));
                asm("fma.rn.f32x2 %0, %1, %2, %0;" : "+l"(a0) : "l"(xA2[2 * d4]),     "l"(e0));
                asm("fma.rn.f32x2 %0, %1, %2, %0;" : "+l"(a1) : "l"(xA2[2 * d4 + 1]), "l"(e1));
                asm("fma.rn.f32x2 %0, %1, %2, %0;" : "+l"(b0) : "l"(xB2[2 * d4]),     "l"(e0));
                asm("fma.rn.f32x2 %0, %1, %2, %0;" : "+l"(b1) : "l"(xB2[2 * d4 + 1]), "l"(e1));
            }
            ull_t sa, sb;
            asm("add.rn.f32x2 %0, %1, %2;" : "=l"(sa) : "l"(a0), "l"(a1));
            asm("add.rn.f32x2 %0, %1, %2;" : "=l"(sb) : "l"(b0), "l"(b1));
            float alo, ahi, blo, bhi;
            asm("mov.b64 {%0, %1}, %2;" : "=f"(alo), "=f"(ahi) : "l"(sa));
            asm("mov.b64 {%0, %1}, %2;" : "=f"(blo), "=f"(bhi) : "l"(sb));
            const float esq = sesq[k];
            const float sAv = fmaf(-2.f, __fadd_rn(alo, ahi), esq);
            const float sBv = fmaf(-2.f, __fadd_rn(blo, bhi), esq);
            const int kk = c * CHUNK + k;
            INS(sAv, kk, s1A, s2A, s3A, k1A, k2A, k3A)
            INS(sBv, kk, s1B, s2B, s3B, k1B, k2B, k3B)
        }
    }
    #undef INS

    const int bkA = resolve(cb, xA2, xsqA, s1A, s2A, s3A, k1A, k2A, k3A);
    const int bkB = resolve(cb, xB2, xsqB, s1B, s2B, s3B, k1B, k2B, k3B);

    // STE epilogue: out = x + (e - x) fp32, BCHW scatter
    const float4* rowA = reinterpret_cast<const float4*>(cb + (size_t)bkA * DIM);
    const float4* rowB = reinterpret_cast<const float4*>(cb + (size_t)bkB * DIM);
    float* opA = out + (size_t)b * (DIM * HW) + sA;
    float* opB = opA + TPB;
    #pragma unroll
    for (int j = 0; j < DIM / 4; j++) {
        float4 qA = __ldg(&rowA[j]);
        float4 qB = __ldg(&rowB[j]);
        float a0, a1, a2, a3, c0, c1, c2, c3;
        asm("mov.b64 {%0, %1}, %2;" : "=f"(a0), "=f"(a1) : "l"(xA2[2 * j]));
        asm("mov.b64 {%0, %1}, %2;" : "=f"(a2), "=f"(a3) : "l"(xA2[2 * j + 1]));
        asm("mov.b64 {%0, %1}, %2;" : "=f"(c0), "=f"(c1) : "l"(xB2[2 * j]));
        asm("mov.b64 {%0, %1}, %2;" : "=f"(c2), "=f"(c3) : "l"(xB2[2 * j + 1]));
        opA[(4 * j + 0) * HW] = __fadd_rn(a0, __fsub_rn(qA.x, a0));
        opA[(4 * j + 1) * HW] = __fadd_rn(a1, __fsub_rn(qA.y, a1));
        opA[(4 * j + 2) * HW] = __fadd_rn(a2, __fsub_rn(qA.z, a2));
        opA[(4 * j + 3) * HW] = __fadd_rn(a3, __fsub_rn(qA.w, a3));
        opB[(4 * j + 0) * HW] = __fadd_rn(c0, __fsub_rn(qB.x, c0));
        opB[(4 * j + 1) * HW] = __fadd_rn(c1, __fsub_rn(qB.y, c1));
        opB[(4 * j + 2) * HW] = __fadd_rn(c2, __fsub_rn(qB.z, c2));
        opB[(4 * j + 3) * HW] = __fadd_rn(c3, __fsub_rn(qB.w, c3));
    }
}

extern "C" void kernel_launch(void* const* d_in, const int* in_sizes, int n_in,
                              void* d_out, int out_size) {
    const float* x  = (const float*)d_in[0];
    const float* cb = (const float*)d_in[1];
    if (n_in >= 2 && in_sizes[0] == NUM_K * DIM && in_sizes[1] == NVEC * DIM) {
        const float* t = x; x = cb; cb = t;
    }
    float* out = (float*)d_out;

    esq_kernel<<<(NUM_K + 127) / 128, 128>>>(cb);
    vq_kernel<<<NVEC / VPB, TPB>>>(x, cb, out);
}

// round 9
// speedup vs baseline: 16.4192x; 1.7738x over previous
#include <cuda_runtime.h>
#include <cstdint>

// BaseVectorQuantizer, exact: dist_k = fp32( fp32(||x||^2+||e_k||^2) - 2*dot ).
// V=1 vector/thread (64 x-regs) -> 5 CTAs/SM for latency hiding.
// Branchless argmin, fma.rn.f32x2 dual-chain dot (R3-validated rounding).

#define NUM_K 1024
#define DIM   64
#define CHUNK 128
#define TPB   128
#define HW    4096
#define NVEC  131072

typedef unsigned long long ull_t;

__device__ float g_esq[NUM_K];

__global__ void esq_kernel(const float* __restrict__ cb) {
    int k = blockIdx.x * blockDim.x + threadIdx.x;
    if (k < NUM_K) {
        float s = 0.f;
        #pragma unroll
        for (int i = 0; i < DIM; i++) {
            float v = cb[k * DIM + i];
            s = __fadd_rn(s, __fmul_rn(v, v));
        }
        g_esq[k] = s;
    }
}

__global__ __launch_bounds__(TPB, 5) void vq_kernel(const float* __restrict__ x_in,
                                                    const float* __restrict__ cb,
                                                    float* __restrict__ out) {
    __shared__ __align__(16) float se[CHUNK * DIM];   // 32 KB row-major
    __shared__ float sesq[CHUNK];

    const int t = threadIdx.x;
    const int n = blockIdx.x * TPB + t;     // vector id
    const int b = n >> 12;
    const int s = n & (HW - 1);
    const float* xp = x_in + (size_t)b * (DIM * HW) + s;

    // x as natural (x_2p, x_2p+1) packed f32x2 pairs; xsq in sequential order
    ull_t x2[DIM / 2];
    float xsq = 0.f;
    #pragma unroll
    for (int p = 0; p < DIM / 2; p++) {
        float v0 = xp[(2 * p) * HW], v1 = xp[(2 * p + 1) * HW];
        xsq = __fadd_rn(xsq, __fmul_rn(v0, v0));
        xsq = __fadd_rn(xsq, __fmul_rn(v1, v1));
        asm("mov.b64 %0, {%1, %2};" : "=l"(x2[p]) : "f"(v0), "f"(v1));
    }

    uint32_t se_base;
    asm("{ .reg .u64 t; cvta.to.shared.u64 t, %1; cvt.u32.u64 %0, t; }"
        : "=r"(se_base) : "l"(se));

    float best = 3.4e38f;
    int   bk   = 0;

    for (int c = 0; c < NUM_K / CHUNK; c++) {
        __syncthreads();
        // coalesced 16B staging, conflict-free
        const float4* src = reinterpret_cast<const float4*>(cb + c * CHUNK * DIM);
        float4* dst = reinterpret_cast<float4*>(se);
        #pragma unroll
        for (int j = 0; j < (CHUNK * DIM / 4) / TPB; j++)
            dst[j * TPB + t] = src[j * TPB + t];
        sesq[t] = g_esq[c * CHUNK + t];
        __syncthreads();

        #pragma unroll 2
        for (int k = 0; k < CHUNK; k++) {
            ull_t a0 = 0ull, a1 = 0ull;            // two packed accumulator chains
            const uint32_t addr = se_base + k * (DIM * 4);
            #pragma unroll
            for (int d4 = 0; d4 < DIM / 4; d4++) {
                ull_t e0, e1;                       // (e4d,e4d+1), (e4d+2,e4d+3)
                asm("ld.shared.v2.u64 {%0, %1}, [%2];"
                    : "=l"(e0), "=l"(e1) : "r"(addr + d4 * 16));
                asm("fma.rn.f32x2 %0, %1, %2, %0;" : "+l"(a0) : "l"(x2[2 * d4]),     "l"(e0));
                asm("fma.rn.f32x2 %0, %1, %2, %0;" : "+l"(a1) : "l"(x2[2 * d4 + 1]), "l"(e1));
            }
            ull_t sa;
            asm("add.rn.f32x2 %0, %1, %2;" : "=l"(sa) : "l"(a0), "l"(a1));
            float lo, hi;
            asm("mov.b64 {%0, %1}, %2;" : "=f"(lo), "=f"(hi) : "l"(sa));
            float dot  = __fadd_rn(lo, hi);
            // dist = round( round(xsq + esq) - 2*dot )  [2*dot exact]
            float dist = __fsub_rn(__fadd_rn(xsq, sesq[k]), __fadd_rn(dot, dot));
            // branchless strict-< (ascending k == first-min tie-break)
            bool p = dist < best;
            best = p ? dist : best;
            bk   = p ? (c * CHUNK + k) : bk;
        }
    }

    // STE epilogue: out = x + (e - x) fp32, BCHW scatter
    const float4* row = reinterpret_cast<const float4*>(cb + (size_t)bk * DIM);
    float* op = out + (size_t)b * (DIM * HW) + s;
    #pragma unroll
    for (int j = 0; j < DIM / 4; j++) {
        float4 qv = __ldg(row + j);
        float x0, x1v, x2v, x3;
        asm("mov.b64 {%0, %1}, %2;" : "=f"(x0),  "=f"(x1v) : "l"(x2[2 * j]));
        asm("mov.b64 {%0, %1}, %2;" : "=f"(x2v), "=f"(x3)  : "l"(x2[2 * j + 1]));
        op[(4 * j + 0) * HW] = __fadd_rn(x0,  __fsub_rn(qv.x, x0));
        op[(4 * j + 1) * HW] = __fadd_rn(x1v, __fsub_rn(qv.y, x1v));
        op[(4 * j + 2) * HW] = __fadd_rn(x2v, __fsub_rn(qv.z, x2v));
        op[(4 * j + 3) * HW] = __fadd_rn(x3,  __fsub_rn(qv.w, x3));
    }
}

extern "C" void kernel_launch(void* const* d_in, const int* in_sizes, int n_in,
                              void* d_out, int out_size) {
    const float* x  = (const float*)d_in[0];
    const float* cb = (const float*)d_in[1];
    if (n_in >= 2 && in_sizes[0] == NUM_K * DIM && in_sizes[1] == NVEC * DIM) {
        const float* t = x; x = cb; cb = t;
    }
    float* out = (float*)d_out;

    esq_kernel<<<(NUM_K + 127) / 128, 128>>>(cb);
    vq_kernel<<<NVEC / TPB, TPB>>>(x, cb, out);
}

// round 13
// speedup vs baseline: 23.3885x; 1.4245x over previous
#include <cuda_runtime.h>
#include <cstdint>

// BaseVectorQuantizer, exact: dist_k = fp32( fp32(||x||^2+||e_k||^2) - 2*dot ).
// V=2 vectors/thread, natural (x_2p,x_2p+1) f32x2 pairs, row-major codebook in
// smem, broadcast LDS.128 feeds 4 fma.rn.f32x2. launch_bounds(128,2) gives
// ptxas ~255 regs to hoist loads (MLP~8) and pipeline across codes.

#define NUM_K 1024
#define DIM   64
#define CHUNK 256
#define TPB   128
#define HW    4096
#define NVEC  131072
#define VPB   256

typedef unsigned long long ull_t;

__device__ float g_esq[NUM_K];

__global__ void esq_kernel(const float* __restrict__ cb) {
    int k = blockIdx.x * blockDim.x + threadIdx.x;
    if (k < NUM_K) {
        float s = 0.f;
        #pragma unroll
        for (int i = 0; i < DIM; i++) {
            float v = cb[k * DIM + i];
            s = __fadd_rn(s, __fmul_rn(v, v));
        }
        g_esq[k] = s;
    }
}

__global__ __launch_bounds__(TPB, 2) void vq_kernel(const float* __restrict__ x_in,
                                                    const float* __restrict__ cb,
                                                    float* __restrict__ out) {
    __shared__ __align__(16) float se[CHUNK * DIM];   // 64 KB row-major
    __shared__ float sesq[CHUNK];

    const int t    = threadIdx.x;
    const int base = blockIdx.x * VPB;
    const int b    = base >> 12;
    const int sA   = (base & (HW - 1)) + t;
    const float* xpA = x_in + (size_t)b * (DIM * HW) + sA;
    const float* xpB = xpA + TPB;

    // x for both vectors as natural packed f32x2 dim-pairs; xsq sequential fp32
    ull_t xA2[DIM / 2], xB2[DIM / 2];
    float xsqA = 0.f, xsqB = 0.f;
    #pragma unroll
    for (int p = 0; p < DIM / 2; p++) {
        float a0 = xpA[(2 * p) * HW], a1 = xpA[(2 * p + 1) * HW];
        float c0 = xpB[(2 * p) * HW], c1 = xpB[(2 * p + 1) * HW];
        xsqA = __fadd_rn(xsqA, __fmul_rn(a0, a0));
        xsqA = __fadd_rn(xsqA, __fmul_rn(a1, a1));
        xsqB = __fadd_rn(xsqB, __fmul_rn(c0, c0));
        xsqB = __fadd_rn(xsqB, __fmul_rn(c1, c1));
        asm("mov.b64 %0, {%1, %2};" : "=l"(xA2[p]) : "f"(a0), "f"(a1));
        asm("mov.b64 %0, {%1, %2};" : "=l"(xB2[p]) : "f"(c0), "f"(c1));
    }

    uint32_t se_base;
    asm("{ .reg .u64 t; cvta.to.shared.u64 t, %1; cvt.u32.u64 %0, t; }"
        : "=r"(se_base) : "l"(se));

    float bestA = 3.4e38f, bestB = 3.4e38f;
    int   bkA = 0, bkB = 0;

    for (int c = 0; c < NUM_K / CHUNK; c++) {
        __syncthreads();
        const float4* src = reinterpret_cast<const float4*>(cb + c * CHUNK * DIM);
        float4* dst = reinterpret_cast<float4*>(se);
        #pragma unroll
        for (int j = 0; j < (CHUNK * DIM / 4) / TPB; j++)
            dst[j * TPB + t] = src[j * TPB + t];
        #pragma unroll
        for (int j = 0; j < CHUNK / TPB; j++)
            sesq[j * TPB + t] = g_esq[c * CHUNK + j * TPB + t];
        __syncthreads();

        #pragma unroll 2
        for (int k = 0; k < CHUNK; k++) {
            ull_t a0 = 0ull, a1 = 0ull, b0 = 0ull, b1 = 0ull;
            const uint32_t addr = se_base + k * (DIM * 4);
            #pragma unroll
            for (int d4 = 0; d4 < DIM / 4; d4++) {
                ull_t e0, e1;   // (e_{4d},e_{4d+1}), (e_{4d+2},e_{4d+3})
                asm("ld.shared.v2.u64 {%0, %1}, [%2];"
                    : "=l"(e0), "=l"(e1) : "r"(addr + d4 * 16));
                asm("fma.rn.f32x2 %0, %1, %2, %0;" : "+l"(a0) : "l"(xA2[2 * d4]),     "l"(e0));
                asm("fma.rn.f32x2 %0, %1, %2, %0;" : "+l"(a1) : "l"(xA2[2 * d4 + 1]), "l"(e1));
                asm("fma.rn.f32x2 %0, %1, %2, %0;" : "+l"(b0) : "l"(xB2[2 * d4]),     "l"(e0));
                asm("fma.rn.f32x2 %0, %1, %2, %0;" : "+l"(b1) : "l"(xB2[2 * d4 + 1]), "l"(e1));
            }
            ull_t sa, sb;
            asm("add.rn.f32x2 %0, %1, %2;" : "=l"(sa) : "l"(a0), "l"(a1));
            asm("add.rn.f32x2 %0, %1, %2;" : "=l"(sb) : "l"(b0), "l"(b1));
            float alo, ahi, blo, bhi;
            asm("mov.b64 {%0, %1}, %2;" : "=f"(alo), "=f"(ahi) : "l"(sa));
            asm("mov.b64 {%0, %1}, %2;" : "=f"(blo), "=f"(bhi) : "l"(sb));
            const float esq  = sesq[k];
            const float dotA = __fadd_rn(alo, ahi);
            const float dotB = __fadd_rn(blo, bhi);
            // dist = round( T - 2*dot ), T = round(xsq+esq); 2*dot exact ->
            // fmaf(-2,dot,T) rounds once == reference fsub(T, 2dot)
            const float dA = fmaf(-2.f, dotA, __fadd_rn(xsqA, esq));
            const float dB = fmaf(-2.f, dotB, __fadd_rn(xsqB, esq));
            const int kk = c * CHUNK + k;
            bool pA = dA < bestA;            // branchless, ascending-k tie-break
            bool pB = dB < bestB;
            bestA = pA ? dA : bestA;  bkA = pA ? kk : bkA;
            bestB = pB ? dB : bestB;  bkB = pB ? kk : bkB;
        }
    }

    // STE epilogue: out = x + (e - x) fp32, BCHW scatter
    const float4* rowA = reinterpret_cast<const float4*>(cb + (size_t)bkA * DIM);
    const float4* rowB = reinterpret_cast<const float4*>(cb + (size_t)bkB * DIM);
    float* opA = out + (size_t)b * (DIM * HW) + sA;
    float* opB = opA + TPB;
    #pragma unroll
    for (int j = 0; j < DIM / 4; j++) {
        float4 qA = __ldg(&rowA[j]);
        float4 qB = __ldg(&rowB[j]);
        float a0, a1, a2, a3, c0, c1, c2, c3;
        asm("mov.b64 {%0, %1}, %2;" : "=f"(a0), "=f"(a1) : "l"(xA2[2 * j]));
        asm("mov.b64 {%0, %1}, %2;" : "=f"(a2), "=f"(a3) : "l"(xA2[2 * j + 1]));
        asm("mov.b64 {%0, %1}, %2;" : "=f"(c0), "=f"(c1) : "l"(xB2[2 * j]));
        asm("mov.b64 {%0, %1}, %2;" : "=f"(c2), "=f"(c3) : "l"(xB2[2 * j + 1]));
        opA[(4 * j + 0) * HW] = __fadd_rn(a0, __fsub_rn(qA.x, a0));
        opA[(4 * j + 1) * HW] = __fadd_rn(a1, __fsub_rn(qA.y, a1));
        opA[(4 * j + 2) * HW] = __fadd_rn(a2, __fsub_rn(qA.z, a2));
        opA[(4 * j + 3) * HW] = __fadd_rn(a3, __fsub_rn(qA.w, a3));
        opB[(4 * j + 0) * HW] = __fadd_rn(c0, __fsub_rn(qB.x, c0));
        opB[(4 * j + 1) * HW] = __fadd_rn(c1, __fsub_rn(qB.y, c1));
        opB[(4 * j + 2) * HW] = __fadd_rn(c2, __fsub_rn(qB.z, c2));
        opB[(4 * j + 3) * HW] = __fadd_rn(c3, __fsub_rn(qB.w, c3));
    }
}

extern "C" void kernel_launch(void* const* d_in, const int* in_sizes, int n_in,
                              void* d_out, int out_size) {
    const float* x  = (const float*)d_in[0];
    const float* cb = (const float*)d_in[1];
    if (n_in >= 2 && in_sizes[0] == NUM_K * DIM && in_sizes[1] == NVEC * DIM) {
        const float* t = x; x = cb; cb = t;
    }
    float* out = (float*)d_out;

    esq_kernel<<<(NUM_K + 127) / 128, 128>>>(cb);
    vq_kernel<<<NVEC / VPB, TPB>>>(x, cb, out);
}